// round 8
// baseline (speedup 1.0000x reference)
#include <cuda_runtime.h>

#define Bv 8
#define Nv 128
#define Tv 256
#define Lv 32
#define Hv 128
#define TTv 224   // T - L

// Scratch (static device globals; allocation-free)
__device__ float g_wsum4[4 * Nv * Hv];     // partial sum_j W_fc[n,j,h] (4 j-slabs)
__device__ float g_bsum[Nv];               // sum_j b_fc[n,j]
__device__ float g_hsum[Bv * Nv * Hv];     // sum_t h[b,n,t,h]/x[b,n,t+L]
__device__ float g_R[Bv * Nv];             // sum_t 1/x[b,n,t+L]

typedef unsigned long long u64t;

__device__ __forceinline__ u64t ffma2(u64t a, u64t b, u64t c) {
    u64t d;
    asm("fma.rn.f32x2 %0, %1, %2, %3;" : "=l"(d) : "l"(a), "l"(b), "l"(c));
    return d;
}
__device__ __forceinline__ u64t pack2(float lo, float hi) {
    u64t u;
    asm("mov.b64 %0, {%1, %2};" : "=l"(u) : "f"(lo), "f"(hi));
    return u;
}
__device__ __forceinline__ float2 unpack2(u64t u) {
    float2 r;
    asm("mov.b64 {%0, %1}, %2;" : "=f"(r.x), "=f"(r.y) : "l"(u));
    return r;
}
__device__ __forceinline__ float tanh_fast(float v) {
    float r;
    asm("tanh.approx.f32 %0, %1;" : "=f"(r) : "f"(v));
    return r;
}
__device__ __forceinline__ float sig_fast(float v) {
    return fmaf(0.5f, tanh_fast(0.5f * v), 0.5f);
}

// ---------------------------------------------------------------------------
// K0: partial Wsum[n,h] over 4 j-slabs; bsum[n]
// ---------------------------------------------------------------------------
__global__ void __launch_bounds__(128) k_prep(const float* __restrict__ Wfc,
                                              const float* __restrict__ bfc) {
    const int n = blockIdx.x, jc = blockIdx.y, h = threadIdx.x;
    const float* p = Wfc + (size_t)n * Nv * Hv + (size_t)jc * 32 * Hv + h;
    float s = 0.f;
#pragma unroll
    for (int j = 0; j < 32; j++) s += p[(size_t)j * Hv];
    g_wsum4[(jc * Nv + n) * Hv + h] = s;

    if (jc == 0) {
        float bvv = bfc[n * Nv + h];
#pragma unroll
        for (int off = 16; off; off >>= 1) bvv += __shfl_xor_sync(0xffffffffu, bvv, off);
        __shared__ float red[4];
        if ((h & 31) == 0) red[h >> 5] = bvv;
        __syncthreads();
        if (h == 0) g_bsum[n] = red[0] + red[1] + red[2] + red[3];
    }
}

// ---------------------------------------------------------------------------
// K1: gates -> h ; Hsum, R ; X_hat via barrier-free per-warp partials.
// FFMA2 paired over l (weights naturally adjacent -> packed ONCE, zero
// per-iteration MOVs), t-block = 4 to keep accumulators at 12 u64 = 24 regs
// (R7's t-block 8 spilled).
// ---------------------------------------------------------------------------
__global__ void __launch_bounds__(128) k_lstm(const float* __restrict__ x,
                                              const float* __restrict__ Wih,
                                              const float* __restrict__ bih,
                                              const float* __restrict__ bhh,
                                              float* __restrict__ outX) {
    __shared__ __align__(16) float xs[Tv];
    __shared__ float2 po[127];            // odd-aligned pairs (x[2k+1], x[2k+2])
    __shared__ float rxs[TTv];
    __shared__ float redX[4 * TTv];       // per-warp X_hat partials
    __shared__ float redR[4];

    const int n = blockIdx.x, b = blockIdx.y;
    const int tid = threadIdx.x;
    const int h = tid, lane = tid & 31, warp = tid >> 5;

    const float* xrow = x + ((size_t)b * Nv + n) * Tv;
    xs[tid] = xrow[tid];
    xs[tid + 128] = xrow[tid + 128];
    __syncthreads();

    if (tid < 127) po[tid] = make_float2(xs[2 * tid + 1], xs[2 * tid + 2]);
    for (int i = tid; i < TTv; i += 128) rxs[i] = 1.0f / xs[i + Lv];

    // Weights for gates {i, g, o} (gate f dead) as pre-packed l-pairs.
    u64t wi2[Lv / 2], wg2[Lv / 2], wo2[Lv / 2];
    {
        const float* Wn = Wih + (size_t)n * 4 * Hv * Lv;
        const float4* p0 = (const float4*)(Wn + ((size_t)0 * Hv + h) * Lv);
        const float4* p2 = (const float4*)(Wn + ((size_t)2 * Hv + h) * Lv);
        const float4* p3 = (const float4*)(Wn + ((size_t)3 * Hv + h) * Lv);
#pragma unroll
        for (int q = 0; q < 8; q++) {
            float4 v0 = p0[q], v2 = p2[q], v3 = p3[q];
            wi2[2 * q] = pack2(v0.x, v0.y); wi2[2 * q + 1] = pack2(v0.z, v0.w);
            wg2[2 * q] = pack2(v2.x, v2.y); wg2[2 * q + 1] = pack2(v2.z, v2.w);
            wo2[2 * q] = pack2(v3.x, v3.y); wo2[2 * q + 1] = pack2(v3.z, v3.w);
        }
    }

    const size_t bb4 = (size_t)n * 4 * Hv;
    const float bi = bih[bb4 + h]          + bhh[bb4 + h];
    const float bg = bih[bb4 + 2 * Hv + h] + bhh[bb4 + 2 * Hv + h];
    const float bo = bih[bb4 + 3 * Hv + h] + bhh[bb4 + 3 * Hv + h];
    const int nh = n * Hv + h;
    const float wsum_h = g_wsum4[nh] + g_wsum4[Nv * Hv + nh] +
                         g_wsum4[2 * Nv * Hv + nh] + g_wsum4[3 * Nv * Hv + nh];
    const float bsum_n = g_bsum[n];
    __syncthreads();

    // R[b,n] = sum_t rxs[t]
    {
        float r = 0.f;
        for (int i = tid; i < TTv; i += 128) r += rxs[i];
#pragma unroll
        for (int off = 16; off; off >>= 1) r += __shfl_xor_sync(0xffffffffu, r, off);
        if (lane == 0) redR[warp] = r;
        __syncthreads();
        if (tid == 0) g_R[b * Nv + n] = redR[0] + redR[1] + redR[2] + redR[3];
    }

    // Bias folded into the lo lane of the accumulator init.
    const u64t bi2z = pack2(bi, 0.f);
    const u64t bg2z = pack2(bg, 0.f);
    const u64t bo2z = pack2(bo, 0.f);

    float hs_acc = 0.f;

    for (int it = 0; it < TTv / 4; it++) {
        const int t0 = it * 4;     // even
        u64t ai[4], ag[4], ao[4];
#pragma unroll
        for (int tt = 0; tt < 4; tt++) { ai[tt] = bi2z; ag[tt] = bg2z; ao[tt] = bo2z; }

        const u64t* pe  = (const u64t*)xs + (t0 >> 1);   // even-aligned pairs
        const u64t* pob = (const u64t*)po + (t0 >> 1);   // odd-aligned pairs

#pragma unroll
        for (int m = 0; m < Lv / 2; m++) {
            const u64t xe0 = pe[m],  xe1 = pe[m + 1];
            const u64t xo0 = pob[m], xo1 = pob[m + 1];
            const u64t wim = wi2[m], wgm = wg2[m], wom = wo2[m];
            ai[0] = ffma2(xe0, wim, ai[0]); ai[2] = ffma2(xe1, wim, ai[2]);
            ai[1] = ffma2(xo0, wim, ai[1]); ai[3] = ffma2(xo1, wim, ai[3]);
            ag[0] = ffma2(xe0, wgm, ag[0]); ag[2] = ffma2(xe1, wgm, ag[2]);
            ag[1] = ffma2(xo0, wgm, ag[1]); ag[3] = ffma2(xo1, wgm, ag[3]);
            ao[0] = ffma2(xe0, wom, ao[0]); ao[2] = ffma2(xe1, wom, ao[2]);
            ao[1] = ffma2(xo0, wom, ao[1]); ao[3] = ffma2(xo1, wom, ao[3]);
        }

        float sx[4];
#pragma unroll
        for (int tt = 0; tt < 4; tt++) {
            const float2 vi = unpack2(ai[tt]);
            const float2 vg = unpack2(ag[tt]);
            const float2 vo = unpack2(ao[tt]);
            const float gi = vi.x + vi.y;
            const float gg = vg.x + vg.y;
            const float go = vo.x + vo.y;
            const float c  = sig_fast(gi) * tanh_fast(gg);
            const float hv = sig_fast(go) * tanh_fast(c);
            hs_acc = fmaf(hv, rxs[t0 + tt], hs_acc);
            sx[tt] = hv * wsum_h;
        }

        // Warp-local reduce over h; lane0 stores per-warp partial. NO barrier.
#pragma unroll
        for (int tt = 0; tt < 4; tt++) {
            float v = sx[tt];
            v += __shfl_xor_sync(0xffffffffu, v, 16);
            v += __shfl_xor_sync(0xffffffffu, v, 8);
            v += __shfl_xor_sync(0xffffffffu, v, 4);
            v += __shfl_xor_sync(0xffffffffu, v, 2);
            v += __shfl_xor_sync(0xffffffffu, v, 1);
            if (lane == 0) redX[warp * TTv + t0 + tt] = v;
        }
    }

    g_hsum[((size_t)b * Nv + n) * Hv + h] = hs_acc;

    // Single barrier, then X_hat epilogue: sum 4 warp partials per t.
    __syncthreads();
    for (int i = tid; i < TTv; i += 128) {
        const float s = redX[i] + redX[TTv + i] + redX[2 * TTv + i] + redX[3 * TTv + i];
        outX[((size_t)b * TTv + i) * Nv + n] = s + bsum_n + 1e-6f;
    }
}

// ---------------------------------------------------------------------------
// K2: G[b,j,n] = (sum_h W_fc[n,j,h]*Hsum[b,n,h] + b_fc[n,j]*R[b,n]) / 224
// ---------------------------------------------------------------------------
__global__ void __launch_bounds__(256) k_gout(const float* __restrict__ Wfc,
                                              const float* __restrict__ bfc,
                                              float* __restrict__ outG) {
    const int n = blockIdx.x;
    const int tid = threadIdx.x;
    const int w = tid >> 5, lane = tid & 31;
    __shared__ __align__(16) float Hs[Bv][Hv];
    __shared__ float Rs[Bv];

    for (int i = tid; i < Bv * Hv; i += 256) {
        int bb = i >> 7, hh = i & 127;
        Hs[bb][hh] = g_hsum[((size_t)bb * Nv + n) * Hv + hh];
    }
    if (tid < Bv) Rs[tid] = g_R[tid * Nv + n];
    __syncthreads();

    float Hl[Bv][4];
#pragma unroll
    for (int bb = 0; bb < Bv; bb++) {
        float4 v = *(const float4*)&Hs[bb][4 * lane];
        Hl[bb][0] = v.x; Hl[bb][1] = v.y; Hl[bb][2] = v.z; Hl[bb][3] = v.w;
    }

    const float sc = 1.0f / (float)TTv;
#pragma unroll 2
    for (int jj = 0; jj < 16; jj++) {
        const int j = w * 16 + jj;
        const float4 wv = ((const float4*)(Wfc + ((size_t)n * Nv + j) * Hv))[lane];
        float acc[Bv];
#pragma unroll
        for (int bb = 0; bb < Bv; bb++) {
            acc[bb] = wv.x * Hl[bb][0] + wv.y * Hl[bb][1] +
                      wv.z * Hl[bb][2] + wv.w * Hl[bb][3];
        }
#pragma unroll
        for (int off = 16; off; off >>= 1) {
#pragma unroll
            for (int bb = 0; bb < Bv; bb++)
                acc[bb] += __shfl_xor_sync(0xffffffffu, acc[bb], off);
        }
        if (lane == 0) {
            const float bj = bfc[n * Nv + j];
#pragma unroll
            for (int bb = 0; bb < Bv; bb++)
                outG[((size_t)bb * Nv + j) * Nv + n] = (acc[bb] + bj * Rs[bb]) * sc;
        }
    }
}

// ---------------------------------------------------------------------------
extern "C" void kernel_launch(void* const* d_in, const int* in_sizes, int n_in,
                              void* d_out, int out_size) {
    (void)in_sizes; (void)n_in; (void)out_size;
    const float* x   = (const float*)d_in[0];
    const float* Wih = (const float*)d_in[1];
    const float* bih = (const float*)d_in[2];
    const float* bhh = (const float*)d_in[3];
    const float* Wfc = (const float*)d_in[4];
    const float* bfc = (const float*)d_in[5];

    float* outG = (float*)d_out;                       // (B, N, N)
    float* outX = outG + (size_t)Bv * Nv * Nv;         // (B, Ttau, N)

    dim3 g0(Nv, 4);
    k_prep<<<g0, 128>>>(Wfc, bfc);
    dim3 g1(Nv, Bv);
    k_lstm<<<g1, 128>>>(x, Wih, bih, bhh, outX);
    k_gout<<<Nv, 256>>>(Wfc, bfc, outG);
}

// round 9
// speedup vs baseline: 1.1013x; 1.1013x over previous
#include <cuda_runtime.h>

#define Bv 8
#define Nv 128
#define Tv 256
#define Lv 32
#define Hv 128
#define TTv 224   // T - L
#define TH  112   // TTv/2 per t-half

// Scratch (static device globals; allocation-free)
__device__ float g_wsum4[4 * Nv * Hv];       // partial sum_j W_fc[n,j,h]
__device__ float g_bsum[Nv];                 // sum_j b_fc[n,j]
__device__ float g_hsum2[2 * Bv * Nv * Hv];  // per-t-half Hsum partials
__device__ float g_R2[2 * Bv * Nv];          // per-t-half R partials

typedef unsigned long long u64t;

__device__ __forceinline__ u64t ffma2(u64t a, u64t b, u64t c) {
    u64t d;
    asm("fma.rn.f32x2 %0, %1, %2, %3;" : "=l"(d) : "l"(a), "l"(b), "l"(c));
    return d;
}
__device__ __forceinline__ u64t pack2(float lo, float hi) {
    u64t u;
    asm("mov.b64 %0, {%1, %2};" : "=l"(u) : "f"(lo), "f"(hi));
    return u;
}
__device__ __forceinline__ float2 unpack2(u64t u) {
    float2 r;
    asm("mov.b64 {%0, %1}, %2;" : "=f"(r.x), "=f"(r.y) : "l"(u));
    return r;
}
__device__ __forceinline__ float tanh_fast(float v) {
    float r;
    asm("tanh.approx.f32 %0, %1;" : "=f"(r) : "f"(v));
    return r;
}
__device__ __forceinline__ float sig_fast(float v) {
    return fmaf(0.5f, tanh_fast(0.5f * v), 0.5f);
}

// ---------------------------------------------------------------------------
// K0: partial Wsum[n,h] over 4 j-slabs; bsum[n]
// ---------------------------------------------------------------------------
__global__ void __launch_bounds__(128) k_prep(const float* __restrict__ Wfc,
                                              const float* __restrict__ bfc) {
    const int n = blockIdx.x, jc = blockIdx.y, h = threadIdx.x;
    const float* p = Wfc + (size_t)n * Nv * Hv + (size_t)jc * 32 * Hv + h;
    float s = 0.f;
#pragma unroll
    for (int j = 0; j < 32; j++) s += p[(size_t)j * Hv];
    g_wsum4[(jc * Nv + n) * Hv + h] = s;

    if (jc == 0) {
        float bvv = bfc[n * Nv + h];
#pragma unroll
        for (int off = 16; off; off >>= 1) bvv += __shfl_xor_sync(0xffffffffu, bvv, off);
        __shared__ float red[4];
        if ((h & 31) == 0) red[h >> 5] = bvv;
        __syncthreads();
        if (h == 0) g_bsum[n] = red[0] + red[1] + red[2] + red[3];
    }
}

// ---------------------------------------------------------------------------
// K1: EXACT R6 inner loop (proven fastest). Only change: each block handles
// HALF the t-range (blockIdx.z in {0,1}) -> 2048 half-duration blocks cut
// wave-quantization loss (2.31 waves of full blocks -> 4.61 of half blocks).
// Hsum/R go to per-half slabs, summed in k_gout.
// ---------------------------------------------------------------------------
__global__ void __launch_bounds__(128) k_lstm(const float* __restrict__ x,
                                              const float* __restrict__ Wih,
                                              const float* __restrict__ bih,
                                              const float* __restrict__ bhh,
                                              float* __restrict__ outX) {
    __shared__ __align__(16) float xs[Tv];
    __shared__ float2 po[127];            // odd-aligned pairs (x[2k+1], x[2k+2])
    __shared__ float rxs[TTv];
    __shared__ float redX[4 * TH];        // per-warp X_hat partials (this half)
    __shared__ float redR[4];

    const int n = blockIdx.x, b = blockIdx.y;
    const int half = blockIdx.z;
    const int toff = half * TH;
    const int tid = threadIdx.x;
    const int h = tid, lane = tid & 31, warp = tid >> 5;

    const float* xrow = x + ((size_t)b * Nv + n) * Tv;
    xs[tid] = xrow[tid];
    xs[tid + 128] = xrow[tid + 128];
    __syncthreads();

    if (tid < 127) po[tid] = make_float2(xs[2 * tid + 1], xs[2 * tid + 2]);
    for (int i = tid; i < TTv; i += 128) rxs[i] = 1.0f / xs[i + Lv];

    // Weights for gates {i, g, o} (gate f is dead) straight into registers.
    float wi[Lv], wg[Lv], wo[Lv];
    {
        const float* Wn = Wih + (size_t)n * 4 * Hv * Lv;
        const float4* p0 = (const float4*)(Wn + ((size_t)0 * Hv + h) * Lv);
        const float4* p2 = (const float4*)(Wn + ((size_t)2 * Hv + h) * Lv);
        const float4* p3 = (const float4*)(Wn + ((size_t)3 * Hv + h) * Lv);
#pragma unroll
        for (int q = 0; q < 8; q++) {
            float4 v0 = p0[q], v2 = p2[q], v3 = p3[q];
            wi[4 * q] = v0.x; wi[4 * q + 1] = v0.y; wi[4 * q + 2] = v0.z; wi[4 * q + 3] = v0.w;
            wg[4 * q] = v2.x; wg[4 * q + 1] = v2.y; wg[4 * q + 2] = v2.z; wg[4 * q + 3] = v2.w;
            wo[4 * q] = v3.x; wo[4 * q + 1] = v3.y; wo[4 * q + 2] = v3.z; wo[4 * q + 3] = v3.w;
        }
    }

    const size_t bb4 = (size_t)n * 4 * Hv;
    const float bi = bih[bb4 + h]          + bhh[bb4 + h];
    const float bg = bih[bb4 + 2 * Hv + h] + bhh[bb4 + 2 * Hv + h];
    const float bo = bih[bb4 + 3 * Hv + h] + bhh[bb4 + 3 * Hv + h];
    const int nh = n * Hv + h;
    const float wsum_h = g_wsum4[nh] + g_wsum4[Nv * Hv + nh] +
                         g_wsum4[2 * Nv * Hv + nh] + g_wsum4[3 * Nv * Hv + nh];
    const float bsum_n = g_bsum[n];
    __syncthreads();

    // R partial over this t-half
    {
        float r = 0.f;
        for (int i = toff + tid; i < toff + TH; i += 128) r += rxs[i];
#pragma unroll
        for (int off = 16; off; off >>= 1) r += __shfl_xor_sync(0xffffffffu, r, off);
        if (lane == 0) redR[warp] = r;
        __syncthreads();
        if (tid == 0)
            g_R2[half * Bv * Nv + b * Nv + n] = redR[0] + redR[1] + redR[2] + redR[3];
    }

    const u64t bi2 = pack2(bi, bi);
    const u64t bg2 = pack2(bg, bg);
    const u64t bo2 = pack2(bo, bo);

    float hs_acc = 0.f;

    for (int it = 0; it < TH / 8; it++) {
        const int t0 = toff + it * 8;     // even
        u64t ai[4], ag[4], ao[4];
#pragma unroll
        for (int p = 0; p < 4; p++) { ai[p] = bi2; ag[p] = bg2; ao[p] = bo2; }

        const u64t* peb = (const u64t*)xs + (t0 >> 1);   // even-aligned pairs
        const u64t* pob = (const u64t*)po + (t0 >> 1);   // odd-aligned pairs

#pragma unroll
        for (int l = 0; l < Lv; l++) {
            const u64t* px = (l & 1) ? (pob + ((l - 1) >> 1)) : (peb + (l >> 1));
            const u64t x0 = px[0], x1 = px[1], x2 = px[2], x3 = px[3];
            const u64t wi2 = pack2(wi[l], wi[l]);
            const u64t wg2 = pack2(wg[l], wg[l]);
            const u64t wo2 = pack2(wo[l], wo[l]);
            ai[0] = ffma2(x0, wi2, ai[0]); ai[1] = ffma2(x1, wi2, ai[1]);
            ai[2] = ffma2(x2, wi2, ai[2]); ai[3] = ffma2(x3, wi2, ai[3]);
            ag[0] = ffma2(x0, wg2, ag[0]); ag[1] = ffma2(x1, wg2, ag[1]);
            ag[2] = ffma2(x2, wg2, ag[2]); ag[3] = ffma2(x3, wg2, ag[3]);
            ao[0] = ffma2(x0, wo2, ao[0]); ao[1] = ffma2(x1, wo2, ao[1]);
            ao[2] = ffma2(x2, wo2, ao[2]); ao[3] = ffma2(x3, wo2, ao[3]);
        }

        float sx[8];
#pragma unroll
        for (int p = 0; p < 4; p++) {
            const float2 vi = unpack2(ai[p]);
            const float2 vg = unpack2(ag[p]);
            const float2 vo = unpack2(ao[p]);
            {
                const float c  = sig_fast(vi.x) * tanh_fast(vg.x);
                const float hv = sig_fast(vo.x) * tanh_fast(c);
                hs_acc = fmaf(hv, rxs[t0 + 2 * p], hs_acc);
                sx[2 * p] = hv * wsum_h;
            }
            {
                const float c  = sig_fast(vi.y) * tanh_fast(vg.y);
                const float hv = sig_fast(vo.y) * tanh_fast(c);
                hs_acc = fmaf(hv, rxs[t0 + 2 * p + 1], hs_acc);
                sx[2 * p + 1] = hv * wsum_h;
            }
        }

        // Warp-local reduce over h; lane0 stores per-warp partial. NO barrier.
#pragma unroll
        for (int tt = 0; tt < 8; tt++) {
            float v = sx[tt];
            v += __shfl_xor_sync(0xffffffffu, v, 16);
            v += __shfl_xor_sync(0xffffffffu, v, 8);
            v += __shfl_xor_sync(0xffffffffu, v, 4);
            v += __shfl_xor_sync(0xffffffffu, v, 2);
            v += __shfl_xor_sync(0xffffffffu, v, 1);
            if (lane == 0) redX[warp * TH + it * 8 + tt] = v;
        }
    }

    g_hsum2[((size_t)half * Bv * Nv + (size_t)b * Nv + n) * Hv + h] = hs_acc;

    // Single barrier, then X_hat epilogue for this half.
    __syncthreads();
    for (int i = tid; i < TH; i += 128) {
        const float s = redX[i] + redX[TH + i] + redX[2 * TH + i] + redX[3 * TH + i];
        outX[((size_t)b * TTv + toff + i) * Nv + n] = s + bsum_n + 1e-6f;
    }
}

// ---------------------------------------------------------------------------
// K2: G[b,j,n] = (sum_h W_fc[n,j,h]*Hsum[b,n,h] + b_fc[n,j]*R[b,n]) / 224
// Hsum/R = sum of the two t-half slabs.
// ---------------------------------------------------------------------------
__global__ void __launch_bounds__(256) k_gout(const float* __restrict__ Wfc,
                                              const float* __restrict__ bfc,
                                              float* __restrict__ outG) {
    const int n = blockIdx.x;
    const int tid = threadIdx.x;
    const int w = tid >> 5, lane = tid & 31;
    __shared__ __align__(16) float Hs[Bv][Hv];
    __shared__ float Rs[Bv];

    const size_t SLAB = (size_t)Bv * Nv * Hv;
    for (int i = tid; i < Bv * Hv; i += 256) {
        int bb = i >> 7, hh = i & 127;
        const size_t idx = ((size_t)bb * Nv + n) * Hv + hh;
        Hs[bb][hh] = g_hsum2[idx] + g_hsum2[SLAB + idx];
    }
    if (tid < Bv) Rs[tid] = g_R2[tid * Nv + n] + g_R2[Bv * Nv + tid * Nv + n];
    __syncthreads();

    float Hl[Bv][4];
#pragma unroll
    for (int bb = 0; bb < Bv; bb++) {
        float4 v = *(const float4*)&Hs[bb][4 * lane];
        Hl[bb][0] = v.x; Hl[bb][1] = v.y; Hl[bb][2] = v.z; Hl[bb][3] = v.w;
    }

    const float sc = 1.0f / (float)TTv;
#pragma unroll 2
    for (int jj = 0; jj < 16; jj++) {
        const int j = w * 16 + jj;
        const float4 wv = ((const float4*)(Wfc + ((size_t)n * Nv + j) * Hv))[lane];
        float acc[Bv];
#pragma unroll
        for (int bb = 0; bb < Bv; bb++) {
            acc[bb] = wv.x * Hl[bb][0] + wv.y * Hl[bb][1] +
                      wv.z * Hl[bb][2] + wv.w * Hl[bb][3];
        }
#pragma unroll
        for (int off = 16; off; off >>= 1) {
#pragma unroll
            for (int bb = 0; bb < Bv; bb++)
                acc[bb] += __shfl_xor_sync(0xffffffffu, acc[bb], off);
        }
        if (lane == 0) {
            const float bj = bfc[n * Nv + j];
#pragma unroll
            for (int bb = 0; bb < Bv; bb++)
                outG[((size_t)bb * Nv + j) * Nv + n] = (acc[bb] + bj * Rs[bb]) * sc;
        }
    }
}

// ---------------------------------------------------------------------------
extern "C" void kernel_launch(void* const* d_in, const int* in_sizes, int n_in,
                              void* d_out, int out_size) {
    (void)in_sizes; (void)n_in; (void)out_size;
    const float* x   = (const float*)d_in[0];
    const float* Wih = (const float*)d_in[1];
    const float* bih = (const float*)d_in[2];
    const float* bhh = (const float*)d_in[3];
    const float* Wfc = (const float*)d_in[4];
    const float* bfc = (const float*)d_in[5];

    float* outG = (float*)d_out;                       // (B, N, N)
    float* outX = outG + (size_t)Bv * Nv * Nv;         // (B, Ttau, N)

    dim3 g0(Nv, 4);
    k_prep<<<g0, 128>>>(Wfc, bfc);
    dim3 g1(Nv, Bv, 2);
    k_lstm<<<g1, 128>>>(x, Wih, bih, bhh, outX);
    k_gout<<<Nv, 256>>>(Wfc, bfc, outG);
}

// round 10
// speedup vs baseline: 1.7633x; 1.6010x over previous
#include <cuda_runtime.h>
#include <cuda_bf16.h>

#define Bv 8
#define Nv 128
#define Tv 256
#define Lv 32
#define Hv 128
#define TTv 224   // T - L

typedef unsigned int u32;

// Scratch (static device globals; allocation-free)
__device__ float g_wsum4[4 * Nv * Hv];     // partial sum_j W_fc[n,j,h]
__device__ float g_bsum[Nv];               // sum_j b_fc[n,j]
__device__ float g_hsum[Bv * Nv * Hv];     // sum_t h[b,n,t,h]/x[b,n,t+L]
__device__ float g_R[Bv * Nv];             // sum_t 1/x[b,n,t+L]
__device__ u32 g_wh[Nv * 384 * 20];        // W_ih bf16-hi, padded rows (20 u32 = 40 bf16)
__device__ u32 g_wl[Nv * 384 * 20];        // W_ih bf16-lo

__device__ __forceinline__ float tanh_fast(float v) {
    float r;
    asm("tanh.approx.f32 %0, %1;" : "=f"(r) : "f"(v));
    return r;
}
__device__ __forceinline__ float sig_fast(float v) {
    return fmaf(0.5f, tanh_fast(0.5f * v), 0.5f);
}
__device__ __forceinline__ void mma16816(float* c, u32 a0, u32 a1, u32 a2, u32 a3,
                                         u32 b0, u32 b1) {
    asm("mma.sync.aligned.m16n8k16.row.col.f32.bf16.bf16.f32 "
        "{%0,%1,%2,%3}, {%4,%5,%6,%7}, {%8,%9}, {%0,%1,%2,%3};"
        : "+f"(c[0]), "+f"(c[1]), "+f"(c[2]), "+f"(c[3])
        : "r"(a0), "r"(a1), "r"(a2), "r"(a3), "r"(b0), "r"(b1));
}

// ---------------------------------------------------------------------------
// K-1: convert W_ih (gates i,g,o) to bf16 hi/lo, padded 40-elem rows.
// Block n, 384 threads (one per gate-h column).
// ---------------------------------------------------------------------------
__global__ void __launch_bounds__(384) k_wprep(const float* __restrict__ Wih) {
    const int n = blockIdx.x, col = threadIdx.x;
    const int g3 = col >> 7, hh = col & 127;
    const int grow = (g3 == 0) ? 0 : (g3 + 1);
    const float* src = Wih + (((size_t)n * 4 + grow) * Hv + hh) * Lv;
    u32* dh = g_wh + ((size_t)n * 384 + col) * 20;
    u32* dl = g_wl + ((size_t)n * 384 + col) * 20;
#pragma unroll
    for (int q = 0; q < 16; q++) {
        float f0 = src[2 * q], f1 = src[2 * q + 1];
        __nv_bfloat16 h0 = __float2bfloat16(f0);
        __nv_bfloat16 h1 = __float2bfloat16(f1);
        __nv_bfloat16 l0 = __float2bfloat16(f0 - __bfloat162float(h0));
        __nv_bfloat16 l1 = __float2bfloat16(f1 - __bfloat162float(h1));
        dh[q] = (u32)__bfloat16_as_ushort(h0) | ((u32)__bfloat16_as_ushort(h1) << 16);
        dl[q] = (u32)__bfloat16_as_ushort(l0) | ((u32)__bfloat16_as_ushort(l1) << 16);
    }
#pragma unroll
    for (int q = 16; q < 20; q++) { dh[q] = 0; dl[q] = 0; }
}

// ---------------------------------------------------------------------------
// K0: partial Wsum[n,h] over 4 j-slabs; bsum[n]
// ---------------------------------------------------------------------------
__global__ void __launch_bounds__(128) k_prep(const float* __restrict__ Wfc,
                                              const float* __restrict__ bfc) {
    const int n = blockIdx.x, jc = blockIdx.y, h = threadIdx.x;
    const float* p = Wfc + (size_t)n * Nv * Hv + (size_t)jc * 32 * Hv + h;
    float s = 0.f;
#pragma unroll
    for (int j = 0; j < 32; j++) s += p[(size_t)j * Hv];
    g_wsum4[(jc * Nv + n) * Hv + h] = s;

    if (jc == 0) {
        float bvv = bfc[n * Nv + h];
#pragma unroll
        for (int off = 16; off; off >>= 1) bvv += __shfl_xor_sync(0xffffffffu, bvv, off);
        __shared__ float red[4];
        if ((h & 31) == 0) red[h >> 5] = bvv;
        __syncthreads();
        if (h == 0) g_bsum[n] = red[0] + red[1] + red[2] + red[3];
    }
}

// ---------------------------------------------------------------------------
// K1: tensor-core gates. Block (n,b), 128 threads, 4 warps.
// Warp w computes gate columns {g*128 + 32w .. +32} (12 n-tiles of 8).
// A frag built from tiny bf16 x tables (A[t][k] = x[t+k] => 3 unique LDS/frag).
// 3 mma passes: Ah*Bh + Al*Bh + Ah*Bl, fp32 accum. Activations register-local.
// ---------------------------------------------------------------------------
#define SM_WH    0
#define SM_WL    30720
#define SM_XS    61440
#define SM_XHA   62464
#define SM_XHB   62992
#define SM_XLA   63520
#define SM_XLB   64048
#define SM_RXS   64576
#define SM_BSM   65472
#define SM_WSM   67008
#define SM_REDX  67520
#define SM_REDR  71104
#define SM_TOT   71136

__global__ void __launch_bounds__(128) k_lstm(const float* __restrict__ x,
                                              const float* __restrict__ bih,
                                              const float* __restrict__ bhh,
                                              float* __restrict__ outX) {
    extern __shared__ __align__(16) unsigned char smraw[];
    float* xs   = (float*)(smraw + SM_XS);
    __nv_bfloat16* xha = (__nv_bfloat16*)(smraw + SM_XHA);
    __nv_bfloat16* xhb = (__nv_bfloat16*)(smraw + SM_XHB);
    __nv_bfloat16* xla = (__nv_bfloat16*)(smraw + SM_XLA);
    __nv_bfloat16* xlb = (__nv_bfloat16*)(smraw + SM_XLB);
    float* rxs  = (float*)(smraw + SM_RXS);
    float* bsm  = (float*)(smraw + SM_BSM);
    float* wsm  = (float*)(smraw + SM_WSM);
    float* redX = (float*)(smraw + SM_REDX);
    float* redR = (float*)(smraw + SM_REDR);

    const int n = blockIdx.x, b = blockIdx.y;
    const int tid = threadIdx.x;
    const int lane = tid & 31, w = tid >> 5;
    const int gid = lane >> 2, tig = lane & 3;

    // ---- stage x ----
    const float* xrow = x + ((size_t)b * Nv + n) * Tv;
    xs[tid] = xrow[tid];
    xs[tid + 128] = xrow[tid + 128];
    __syncthreads();

    // ---- bf16 split tables (xhb[i] = xh[i+1] for odd-aligned pairs) ----
#pragma unroll
    for (int rep = 0; rep < 2; rep++) {
        const int i = tid + rep * 128;
        const float f = xs[i];
        const __nv_bfloat16 hh = __float2bfloat16(f);
        const __nv_bfloat16 ll = __float2bfloat16(f - __bfloat162float(hh));
        xha[i] = hh; xla[i] = ll;
        if (i > 0) { xhb[i - 1] = hh; xlb[i - 1] = ll; }
    }
    for (int i = tid; i < TTv; i += 128) rxs[i] = 1.0f / xs[i + Lv];

    // ---- stage W bf16 hi/lo (flat copy, padded rows match gmem layout) ----
    {
        const int4* sh = (const int4*)(g_wh + (size_t)n * 7680);
        const int4* sl = (const int4*)(g_wl + (size_t)n * 7680);
        int4* dh = (int4*)(smraw + SM_WH);
        int4* dl = (int4*)(smraw + SM_WL);
#pragma unroll
        for (int q = 0; q < 15; q++) {
            dh[tid + q * 128] = sh[tid + q * 128];
            dl[tid + q * 128] = sl[tid + q * 128];
        }
    }

    // ---- biases and wsum into smem ----
#pragma unroll
    for (int rep = 0; rep < 3; rep++) {
        const int col = tid + rep * 128;
        const int g3 = col >> 7, hh = col & 127;
        const int grow = (g3 == 0) ? 0 : (g3 + 1);
        const size_t idx = (size_t)n * 4 * Hv + grow * Hv + hh;
        bsm[col] = bih[idx] + bhh[idx];
    }
    {
        const int nh = n * Hv + tid;
        wsm[tid] = g_wsum4[nh] + g_wsum4[Nv * Hv + nh] +
                   g_wsum4[2 * Nv * Hv + nh] + g_wsum4[3 * Nv * Hv + nh];
    }
    __syncthreads();

    // ---- R[b,n] ----
    {
        float r = 0.f;
        for (int i = tid; i < TTv; i += 128) r += rxs[i];
#pragma unroll
        for (int off = 16; off; off >>= 1) r += __shfl_xor_sync(0xffffffffu, r, off);
        if (lane == 0) redR[w] = r;
        __syncthreads();
        if (tid == 0) g_R[b * Nv + n] = redR[0] + redR[1] + redR[2] + redR[3];
    }

    // ---- per-thread constants ----
    float wsum8[8];
#pragma unroll
    for (int j = 0; j < 4; j++)
#pragma unroll
        for (int cc = 0; cc < 2; cc++)
            wsum8[j * 2 + cc] = wsm[(w << 5) + j * 8 + (tig << 1) + cc];

    const int odd = gid & 1;
    const int pb = gid + 2 * tig - odd;          // even
    const u32* xaH = (const u32*)(odd ? (void*)xhb : (void*)xha);
    const u32* xaL = (const u32*)(odd ? (void*)xlb : (void*)xla);
    const u32* WhU = (const u32*)(smraw + SM_WH);
    const u32* WlU = (const u32*)(smraw + SM_WL);

    float hs[8];
#pragma unroll
    for (int e = 0; e < 8; e++) hs[e] = 0.f;

    // ================= main loop: 14 slabs of 16 t, NO barriers =============
    for (int slab = 0; slab < 14; slab++) {
        const int t0 = slab * 16;
        const int q = (t0 + pb) >> 1;

        u32 Ah[5], Al[5];
#pragma unroll
        for (int i = 0; i < 5; i++) { Ah[i] = xaH[q + 4 * i]; Al[i] = xaL[q + 4 * i]; }

        float c[48];
        // C init = biases (per tile: cols 2tig, 2tig+1; both rows share)
#pragma unroll
        for (int g3 = 0; g3 < 3; g3++)
#pragma unroll
            for (int j = 0; j < 4; j++) {
                const int col0 = g3 * 128 + (w << 5) + (j << 3) + (tig << 1);
                const float b0 = bsm[col0], b1 = bsm[col0 + 1];
                float* ct = c + (g3 * 4 + j) * 4;
                ct[0] = b0; ct[1] = b1; ct[2] = b0; ct[3] = b1;
            }

        // MMA: 12 tiles x 2 k-steps x 3 passes
#pragma unroll
        for (int g3 = 0; g3 < 3; g3++)
#pragma unroll
            for (int j = 0; j < 4; j++) {
                const int colb = g3 * 128 + (w << 5) + (j << 3) + gid;
                const u32* br_h = WhU + colb * 20;
                const u32* br_l = WlU + colb * 20;
                float* ct = c + (g3 * 4 + j) * 4;
#pragma unroll
                for (int ks = 0; ks < 2; ks++) {
                    const u32 bh0 = br_h[8 * ks + tig], bh1 = br_h[8 * ks + tig + 4];
                    const u32 bl0 = br_l[8 * ks + tig], bl1 = br_l[8 * ks + tig + 4];
                    const u32 a0 = Ah[2 * ks], a12 = Ah[2 * ks + 1], a3 = Ah[2 * ks + 2];
                    const u32 e0 = Al[2 * ks], e12 = Al[2 * ks + 1], e3 = Al[2 * ks + 2];
                    mma16816(ct, a0, a12, a12, a3, bh0, bh1);
                    mma16816(ct, e0, e12, e12, e3, bh0, bh1);
                    mma16816(ct, a0, a12, a12, a3, bl0, bl1);
                }
            }

        // Epilogue: register-local activations
        const float rx0 = rxs[t0 + gid];
        const float rx1 = rxs[t0 + gid + 8];
        float sxr0 = 0.f, sxr1 = 0.f;
#pragma unroll
        for (int j = 0; j < 4; j++)
#pragma unroll
            for (int cc = 0; cc < 2; cc++) {
                const float ws = wsum8[j * 2 + cc];
#pragma unroll
                for (int rr = 0; rr < 2; rr++) {
                    const int idx = rr * 2 + cc;
                    const float pi = c[(0 * 4 + j) * 4 + idx];
                    const float pg = c[(1 * 4 + j) * 4 + idx];
                    const float po = c[(2 * 4 + j) * 4 + idx];
                    const float cv = sig_fast(pi) * tanh_fast(pg);
                    const float hv = sig_fast(po) * tanh_fast(cv);
                    hs[j * 2 + cc] = fmaf(hv, rr ? rx1 : rx0, hs[j * 2 + cc]);
                    if (rr) sxr1 = fmaf(hv, ws, sxr1);
                    else    sxr0 = fmaf(hv, ws, sxr0);
                }
            }
        // reduce over tig (h within warp): xor 1, 2
        sxr0 += __shfl_xor_sync(0xffffffffu, sxr0, 1);
        sxr0 += __shfl_xor_sync(0xffffffffu, sxr0, 2);
        sxr1 += __shfl_xor_sync(0xffffffffu, sxr1, 1);
        sxr1 += __shfl_xor_sync(0xffffffffu, sxr1, 2);
        if (tig == 0) {
            redX[w * TTv + t0 + gid] = sxr0;
            redX[w * TTv + t0 + gid + 8] = sxr1;
        }
    }

    // ---- Hsum: reduce over gid (xor 4,8,16), lanes gid==0 store ----
#pragma unroll
    for (int e = 0; e < 8; e++) {
        float v = hs[e];
        v += __shfl_xor_sync(0xffffffffu, v, 4);
        v += __shfl_xor_sync(0xffffffffu, v, 8);
        v += __shfl_xor_sync(0xffffffffu, v, 16);
        hs[e] = v;
    }
    if (gid == 0) {
#pragma unroll
        for (int j = 0; j < 4; j++)
#pragma unroll
            for (int cc = 0; cc < 2; cc++) {
                const int h = (w << 5) + j * 8 + (tig << 1) + cc;
                g_hsum[((size_t)b * Nv + n) * Hv + h] = hs[j * 2 + cc];
            }
    }

    // ---- X_hat: sum 4 warp partials per t ----
    const float bsum_n = g_bsum[n];
    __syncthreads();
    for (int i = tid; i < TTv; i += 128) {
        const float s = redX[i] + redX[TTv + i] + redX[2 * TTv + i] + redX[3 * TTv + i];
        outX[((size_t)b * TTv + i) * Nv + n] = s + bsum_n + 1e-6f;
    }
}

// ---------------------------------------------------------------------------
// K2: G[b,j,n] = (sum_h W_fc[n,j,h]*Hsum[b,n,h] + b_fc[n,j]*R[b,n]) / 224
// ---------------------------------------------------------------------------
__global__ void __launch_bounds__(256) k_gout(const float* __restrict__ Wfc,
                                              const float* __restrict__ bfc,
                                              float* __restrict__ outG) {
    const int n = blockIdx.x;
    const int tid = threadIdx.x;
    const int w = tid >> 5, lane = tid & 31;
    __shared__ __align__(16) float Hs[Bv][Hv];
    __shared__ float Rs[Bv];

    for (int i = tid; i < Bv * Hv; i += 256) {
        int bb = i >> 7, hh = i & 127;
        Hs[bb][hh] = g_hsum[((size_t)bb * Nv + n) * Hv + hh];
    }
    if (tid < Bv) Rs[tid] = g_R[tid * Nv + n];
    __syncthreads();

    float Hl[Bv][4];
#pragma unroll
    for (int bb = 0; bb < Bv; bb++) {
        float4 v = *(const float4*)&Hs[bb][4 * lane];
        Hl[bb][0] = v.x; Hl[bb][1] = v.y; Hl[bb][2] = v.z; Hl[bb][3] = v.w;
    }

    const float sc = 1.0f / (float)TTv;
#pragma unroll 2
    for (int jj = 0; jj < 16; jj++) {
        const int j = w * 16 + jj;
        const float4 wv = ((const float4*)(Wfc + ((size_t)n * Nv + j) * Hv))[lane];
        float acc[Bv];
#pragma unroll
        for (int bb = 0; bb < Bv; bb++) {
            acc[bb] = wv.x * Hl[bb][0] + wv.y * Hl[bb][1] +
                      wv.z * Hl[bb][2] + wv.w * Hl[bb][3];
        }
#pragma unroll
        for (int off = 16; off; off >>= 1) {
#pragma unroll
            for (int bb = 0; bb < Bv; bb++)
                acc[bb] += __shfl_xor_sync(0xffffffffu, acc[bb], off);
        }
        if (lane == 0) {
            const float bj = bfc[n * Nv + j];
#pragma unroll
            for (int bb = 0; bb < Bv; bb++)
                outG[((size_t)bb * Nv + j) * Nv + n] = (acc[bb] + bj * Rs[bb]) * sc;
        }
    }
}

// ---------------------------------------------------------------------------
extern "C" void kernel_launch(void* const* d_in, const int* in_sizes, int n_in,
                              void* d_out, int out_size) {
    (void)in_sizes; (void)n_in; (void)out_size;
    const float* x   = (const float*)d_in[0];
    const float* Wih = (const float*)d_in[1];
    const float* bih = (const float*)d_in[2];
    const float* bhh = (const float*)d_in[3];
    const float* Wfc = (const float*)d_in[4];
    const float* bfc = (const float*)d_in[5];

    float* outG = (float*)d_out;                       // (B, N, N)
    float* outX = outG + (size_t)Bv * Nv * Nv;         // (B, Ttau, N)

    cudaFuncSetAttribute(k_lstm, cudaFuncAttributeMaxDynamicSharedMemorySize, SM_TOT);

    k_wprep<<<Nv, 384>>>(Wih);
    dim3 g0(Nv, 4);
    k_prep<<<g0, 128>>>(Wfc, bfc);
    dim3 g1(Nv, Bv);
    k_lstm<<<g1, 128, SM_TOT>>>(x, bih, bhh, outX);
    k_gout<<<Nv, 256>>>(Wfc, bfc, outG);
}